// round 1
// baseline (speedup 1.0000x reference)
#include <cuda_runtime.h>
#include <math.h>

// Problem constants
#define B_ 8192
#define D_ 4096
#define E_ 512

// Scratch (device globals: no cudaMalloc allowed)
__device__ float  g_dot[(size_t)B_ * E_];   // 16M floats = 64MB
__device__ float  g_norm[E_];               // ||e||^2
__device__ float  g_xnorm[B_];              // ||x||^2
__device__ int    g_idx[B_];
__device__ int    g_hist[E_];
__device__ double g_loss;

// ---------------------------------------------------------------------------
__global__ void k_init() {
    int t = threadIdx.x;
    if (t < E_) g_hist[t] = 0;
    if (t == 0) g_loss = 0.0;
}

// ---------------------------------------------------------------------------
// Codebook row norms: one block per code row
__global__ __launch_bounds__(256) void k_norms(const float* __restrict__ cb) {
    int e = blockIdx.x;
    const float* row = cb + (size_t)e * D_;
    float s = 0.f;
    for (int d = threadIdx.x; d < D_; d += 256) {
        float v = row[d];
        s += v * v;
    }
    __shared__ float sh[256];
    sh[threadIdx.x] = s;
    __syncthreads();
    for (int st = 128; st > 0; st >>= 1) {
        if (threadIdx.x < st) sh[threadIdx.x] += sh[threadIdx.x + st];
        __syncthreads();
    }
    if (threadIdx.x == 0) g_norm[e] = sh[0];
}

// Input row norms: one block per 1 input row (8192 blocks)
__global__ __launch_bounds__(256) void k_xnorms(const float* __restrict__ X) {
    int b = blockIdx.x;
    const float4* row = reinterpret_cast<const float4*>(X + (size_t)b * D_);
    float s = 0.f;
    for (int i = threadIdx.x; i < D_ / 4; i += 256) {
        float4 v = row[i];
        s += v.x * v.x + v.y * v.y + v.z * v.z + v.w * v.w;
    }
    __shared__ float sh[256];
    sh[threadIdx.x] = s;
    __syncthreads();
    for (int st = 128; st > 0; st >>= 1) {
        if (threadIdx.x < st) sh[threadIdx.x] += sh[threadIdx.x + st];
        __syncthreads();
    }
    if (threadIdx.x == 0) g_xnorm[b] = sh[0];
}

// ---------------------------------------------------------------------------
// fp32 GEMM-NT: dot[b][e] = sum_k X[b][k] * C[e][k]
// Tile 128x128, BK=16, 256 threads, 8x8 per thread.
#define BM 128
#define BN 128
#define BK 16
#define TM 8
#define TN 8

__global__ __launch_bounds__(256, 2) void k_gemm(const float* __restrict__ A,
                                                 const float* __restrict__ Cb) {
    __shared__ float As[BK][BM];   // no pad: keep 16B alignment for LDS.128 frag reads
    __shared__ float Bs[BK][BN];

    const int bx = blockIdx.x;   // E tile: 0..3
    const int by = blockIdx.y;   // B tile: 0..63
    const int tid = threadIdx.x;
    const int tx = tid & 15;     // 0..15 (cols / E)
    const int ty = tid >> 4;     // 0..15 (rows / B)

    const float* Ab = A  + (size_t)by * BM * D_;
    const float* Bb = Cb + (size_t)bx * BN * D_;

    float acc[TM][TN];
#pragma unroll
    for (int i = 0; i < TM; i++)
#pragma unroll
        for (int j = 0; j < TN; j++) acc[i][j] = 0.f;

    const int lrow  = tid >> 2;        // 0..63
    const int lcol  = (tid & 3) * 4;   // 0,4,8,12

    for (int kt = 0; kt < D_; kt += BK) {
#pragma unroll
        for (int r = 0; r < 2; r++) {
            int row = lrow + r * 64;
            float4 va = *reinterpret_cast<const float4*>(Ab + (size_t)row * D_ + kt + lcol);
            As[lcol + 0][row] = va.x;
            As[lcol + 1][row] = va.y;
            As[lcol + 2][row] = va.z;
            As[lcol + 3][row] = va.w;
            float4 vb = *reinterpret_cast<const float4*>(Bb + (size_t)row * D_ + kt + lcol);
            Bs[lcol + 0][row] = vb.x;
            Bs[lcol + 1][row] = vb.y;
            Bs[lcol + 2][row] = vb.z;
            Bs[lcol + 3][row] = vb.w;
        }
        __syncthreads();

#pragma unroll
        for (int k = 0; k < BK; k++) {
            float4 a0 = *reinterpret_cast<const float4*>(&As[k][ty * TM]);
            float4 a1 = *reinterpret_cast<const float4*>(&As[k][ty * TM + 4]);
            float4 b0 = *reinterpret_cast<const float4*>(&Bs[k][tx * TN]);
            float4 b1 = *reinterpret_cast<const float4*>(&Bs[k][tx * TN + 4]);
            float a[TM] = {a0.x, a0.y, a0.z, a0.w, a1.x, a1.y, a1.z, a1.w};
            float b[TN] = {b0.x, b0.y, b0.z, b0.w, b1.x, b1.y, b1.z, b1.w};
#pragma unroll
            for (int i = 0; i < TM; i++)
#pragma unroll
                for (int j = 0; j < TN; j++) acc[i][j] += a[i] * b[j];
        }
        __syncthreads();
    }

    // Write dots
#pragma unroll
    for (int i = 0; i < TM; i++) {
        int gb = by * BM + ty * TM + i;
        float* dst = g_dot + (size_t)gb * E_ + bx * BN + tx * TN;
#pragma unroll
        for (int j = 0; j < TN; j += 4) {
            float4 v = make_float4(acc[i][j], acc[i][j + 1], acc[i][j + 2], acc[i][j + 3]);
            *reinterpret_cast<float4*>(dst + j) = v;
        }
    }
}

// ---------------------------------------------------------------------------
// argmin per row: one warp per row. Replicate reference rounding order:
//   dist = (||x||^2 + ||e||^2) - 2*dot      (jnp: a + b - c  ->  (a+b) - c)
// First-index tie-break (jnp.argmin semantics).
__global__ __launch_bounds__(256) void k_argmin() {
    int warp = (blockIdx.x * 256 + threadIdx.x) >> 5;
    int lane = threadIdx.x & 31;
    if (warp >= B_) return;
    const float* dp = g_dot + (size_t)warp * E_;
    float xn = g_xnorm[warp];
    float best = INFINITY;
    int bidx = E_;
    for (int e = lane; e < E_; e += 32) {
        float v = (xn + g_norm[e]) - 2.f * dp[e];
        if (v < best) { best = v; bidx = e; }   // e strictly increasing -> first-min kept
    }
#pragma unroll
    for (int off = 16; off > 0; off >>= 1) {
        float ov = __shfl_down_sync(0xffffffffu, best, off);
        int   oi = __shfl_down_sync(0xffffffffu, bidx, off);
        if (ov < best || (ov == best && oi < bidx)) { best = ov; bidx = oi; }
    }
    if (lane == 0) g_idx[warp] = bidx;
}

// ---------------------------------------------------------------------------
// Per-row outputs: quantized_st, one-hot encodings, histogram, fp64 loss sum.
// outQ / outEnc are NOT 16B-aligned (offset +1 / +B*D+2 floats) -> scalar stores.
__global__ __launch_bounds__(256) void k_out(const float* __restrict__ X,
                                             const float* __restrict__ Cb,
                                             float* __restrict__ outQ,
                                             float* __restrict__ outEnc) {
    int b = blockIdx.x;
    int t = threadIdx.x;
    int idx = g_idx[b];

    if (t == 0) atomicAdd(&g_hist[idx], 1);

    // one-hot encodings row
    for (int e = t; e < E_; e += 256)
        outEnc[(size_t)b * E_ + e] = (e == idx) ? 1.f : 0.f;

    const float4* x4 = reinterpret_cast<const float4*>(X  + (size_t)b   * D_);
    const float4* q4 = reinterpret_cast<const float4*>(Cb + (size_t)idx * D_);
    float* o = outQ + (size_t)b * D_;

    float ls = 0.f;
    for (int i = t; i < D_ / 4; i += 256) {
        float4 x = x4[i];
        float4 q = q4[i];
        float dx = q.x - x.x, dy = q.y - x.y, dz = q.z - x.z, dw = q.w - x.w;
        // same expression as reference STE: x + (q - x)
        o[4 * i + 0] = x.x + dx;
        o[4 * i + 1] = x.y + dy;
        o[4 * i + 2] = x.z + dz;
        o[4 * i + 3] = x.w + dw;
        ls += dx * dx + dy * dy + dz * dz + dw * dw;
    }

    __shared__ float sh[256];
    sh[t] = ls;
    __syncthreads();
    for (int st = 128; st > 0; st >>= 1) {
        if (t < st) sh[t] += sh[t + st];
        __syncthreads();
    }
    if (t == 0) atomicAdd(&g_loss, (double)sh[0]);
}

// ---------------------------------------------------------------------------
__global__ __launch_bounds__(512) void k_final(float* __restrict__ out) {
    __shared__ double sh[512];
    int t = threadIdx.x;
    double p = (double)g_hist[t] / (double)B_;
    sh[t] = p * log(p + 1e-10);
    __syncthreads();
    for (int st = 256; st > 0; st >>= 1) {
        if (t < st) sh[t] += sh[t + st];
        __syncthreads();
    }
    if (t == 0) {
        // loss = q_latent + 0.25 * e_latent, both equal mse(q, x)
        double mse = g_loss / ((double)B_ * (double)D_);
        out[0] = (float)(1.25 * mse);
        out[1 + (size_t)B_ * D_] = (float)exp(-sh[0]);
    }
}

// ---------------------------------------------------------------------------
extern "C" void kernel_launch(void* const* d_in, const int* in_sizes, int n_in,
                              void* d_out, int out_size) {
    (void)in_sizes; (void)n_in; (void)out_size;
    const float* X  = (const float*)d_in[0];   // [8192, 8,8,8,8] -> [8192,4096]
    const float* Cb = (const float*)d_in[1];   // [512, 4096]
    float* out = (float*)d_out;

    float* outQ   = out + 1;                              // quantized_st
    float* outEnc = out + 1 + (size_t)B_ * D_ + 1;        // encodings

    k_init<<<1, 512>>>();
    k_norms<<<E_, 256>>>(Cb);
    k_xnorms<<<B_, 256>>>(X);
    dim3 gg(E_ / BN, B_ / BM);
    k_gemm<<<gg, 256>>>(X, Cb);
    k_argmin<<<B_ / 8, 256>>>();
    k_out<<<B_, 256>>>(X, Cb, outQ, outEnc);
    k_final<<<1, 512>>>(out);
}

// round 5
// speedup vs baseline: 4.6598x; 4.6598x over previous
#include <cuda_runtime.h>
#include <cuda_bf16.h>
#include <math.h>
#include <stdint.h>

#define B_ 8192
#define D_ 4096
#define E_ 512
#define MARGIN 3.0f

// ---------------- scratch (device globals; no cudaMalloc allowed) ----------
__device__ __align__(16) __nv_bfloat16 g_Xb[(size_t)B_ * D_];   // 64MB
__device__ __align__(16) __nv_bfloat16 g_Cb[(size_t)E_ * D_];   // 4MB
__device__ __align__(16) float g_dist[(size_t)B_ * E_];         // 16MB approx distances
__device__ float  g_norm[E_];      // exact fp32 ||e||^2
__device__ int    g_idx[B_];
__device__ int    g_ncand[B_];
__device__ int    g_cand[B_][8];
__device__ int    g_hist[E_];
__device__ double g_loss;

// ---------------- PTX helpers ----------------------------------------------
__device__ __forceinline__ uint32_t smem_u32(const void* p) {
    uint32_t a;
    asm("{ .reg .u64 t; cvta.to.shared.u64 t, %1; cvt.u32.u64 %0, t; }" : "=r"(a) : "l"(p));
    return a;
}
__device__ __forceinline__ void cp16(uint32_t dst, const void* src) {
    asm volatile("cp.async.cg.shared.global [%0], [%1], 16;" :: "r"(dst), "l"(src) : "memory");
}
__device__ __forceinline__ void ldmx4(uint32_t* f, uint32_t addr) {
    asm volatile("ldmatrix.sync.aligned.m8n8.x4.shared.b16 {%0,%1,%2,%3}, [%4];"
                 : "=r"(f[0]), "=r"(f[1]), "=r"(f[2]), "=r"(f[3]) : "r"(addr));
}
__device__ __forceinline__ void mma16816(float* c, const uint32_t* a,
                                         uint32_t b0, uint32_t b1) {
    asm volatile(
        "mma.sync.aligned.m16n8k16.row.col.f32.bf16.bf16.f32 "
        "{%0,%1,%2,%3}, {%4,%5,%6,%7}, {%8,%9}, {%0,%1,%2,%3};"
        : "+f"(c[0]), "+f"(c[1]), "+f"(c[2]), "+f"(c[3])
        : "r"(a[0]), "r"(a[1]), "r"(a[2]), "r"(a[3]), "r"(b0), "r"(b1));
}

// ---------------- small kernels ---------------------------------------------
__global__ void k_init() {
    int i = blockIdx.x * 256 + threadIdx.x;
    if (i < E_) g_hist[i] = 0;
    for (int r = i; r < B_; r += gridDim.x * 256) g_ncand[r] = 0;
    if (i == 0) g_loss = 0.0;
}

// fp32 -> bf16 conversion of X (8 floats / thread, vectorized I/O)
__global__ __launch_bounds__(256) void k_convX(const float* __restrict__ X) {
    size_t i = (size_t)blockIdx.x * 256 + threadIdx.x;
    const float4* x4 = reinterpret_cast<const float4*>(X);
    float4 a = x4[2 * i], b = x4[2 * i + 1];
    __nv_bfloat162 p0 = __float22bfloat162_rn(make_float2(a.x, a.y));
    __nv_bfloat162 p1 = __float22bfloat162_rn(make_float2(a.z, a.w));
    __nv_bfloat162 p2 = __float22bfloat162_rn(make_float2(b.x, b.y));
    __nv_bfloat162 p3 = __float22bfloat162_rn(make_float2(b.z, b.w));
    uint4 v;
    v.x = ((uint32_t)__bfloat16_as_ushort(p0.y) << 16) | __bfloat16_as_ushort(p0.x);
    v.y = ((uint32_t)__bfloat16_as_ushort(p1.y) << 16) | __bfloat16_as_ushort(p1.x);
    v.z = ((uint32_t)__bfloat16_as_ushort(p2.y) << 16) | __bfloat16_as_ushort(p2.x);
    v.w = ((uint32_t)__bfloat16_as_ushort(p3.y) << 16) | __bfloat16_as_ushort(p3.x);
    reinterpret_cast<uint4*>(g_Xb)[i] = v;
}

// codebook: exact fp32 norms + bf16 copy
__global__ __launch_bounds__(256) void k_normsC(const float* __restrict__ cb) {
    int e = blockIdx.x;
    const float* row = cb + (size_t)e * D_;
    __nv_bfloat16* brow = g_Cb + (size_t)e * D_;
    float s = 0.f;
    for (int d = threadIdx.x; d < D_; d += 256) {
        float v = row[d];
        s += v * v;
        brow[d] = __float2bfloat16_rn(v);
    }
    __shared__ float sh[256];
    sh[threadIdx.x] = s;
    __syncthreads();
    for (int st = 128; st > 0; st >>= 1) {
        if (threadIdx.x < st) sh[threadIdx.x] += sh[threadIdx.x + st];
        __syncthreads();
    }
    if (threadIdx.x == 0) g_norm[e] = sh[0];
}

// ---------------- mma.sync bf16 GEMM ----------------------------------------
// CTA tile 128x128, BK=32, 3-stage cp.async pipeline, 8 warps (2x4), each 64x32.
// SMEM (dynamic): stage s at s*16KB: [A 128x32bf16 8KB][B 128x32bf16 8KB];
// cns (fp32[128]) at 48KB. Total 49664 bytes.
// Swizzle: row r (64B), 16B-unit u: phys u' = u ^ ((r>>1)&3).
#define BK 32
#define SMEM_GEMM (3 * 16384 + 512)

__device__ __forceinline__ void load_tile(uint32_t as, int tid,
                                          const __nv_bfloat16* __restrict__ gA,
                                          const __nv_bfloat16* __restrict__ gB,
                                          int kk) {
    uint32_t bs = as + 8192;
#pragma unroll
    for (int i = 0; i < 2; i++) {
        int id = tid + 256 * i;
        int r = id >> 2, u = id & 3;
        uint32_t off = (uint32_t)(r * 64 + ((u ^ ((r >> 1) & 3)) << 4));
        const __nv_bfloat16* sa = gA + (size_t)r * D_ + kk + u * 8;
        const __nv_bfloat16* sb = gB + (size_t)r * D_ + kk + u * 8;
        cp16(as + off, sa);
        cp16(bs + off, sb);
    }
}

__global__ __launch_bounds__(256, 2) void k_gemm_mma() {
    extern __shared__ char smem[];
    uint32_t sb = smem_u32(smem);
    float* cns = (float*)(smem + 49152);
    int tid = threadIdx.x, wid = tid >> 5, lane = tid & 31;
    int n0 = blockIdx.x * 128, m0 = blockIdx.y * 128;
    int wm = (wid >> 2) * 64, wn = (wid & 3) * 32;

    const __nv_bfloat16* gA = g_Xb + (size_t)m0 * D_;
    const __nv_bfloat16* gB = g_Cb + (size_t)n0 * D_;
    for (int i = tid; i < 128; i += 256) cns[i] = g_norm[n0 + i];

    float acc[4][4][4];
#pragma unroll
    for (int a = 0; a < 4; a++)
#pragma unroll
        for (int b = 0; b < 4; b++)
#pragma unroll
            for (int c = 0; c < 4; c++) acc[a][b][c] = 0.f;

    // prologue: stage 0,1
    load_tile(sb, tid, gA, gB, 0);
    asm volatile("cp.async.commit_group;" ::: "memory");
    load_tile(sb + 16384, tid, gA, gB, BK);
    asm volatile("cp.async.commit_group;" ::: "memory");

    int s_load = 2, s_cmp = 0;
    const int NKT = D_ / BK;   // 128
    for (int kt = 0; kt < NKT; kt++) {
        asm volatile("cp.async.wait_group 1;" ::: "memory");
        __syncthreads();
        if (kt + 2 < NKT) load_tile(sb + s_load * 16384, tid, gA, gB, (kt + 2) * BK);
        asm volatile("cp.async.commit_group;" ::: "memory");
        if (++s_load == 3) s_load = 0;

        uint32_t as = sb + s_cmp * 16384;
        uint32_t bs = as + 8192;
        if (++s_cmp == 3) s_cmp = 0;

#pragma unroll
        for (int ks = 0; ks < 2; ks++) {
            uint32_t af[4][4], bf[2][4];
#pragma unroll
            for (int mi = 0; mi < 4; mi++) {
                int r = wm + 16 * mi + (lane & 7) + 8 * ((lane >> 3) & 1);
                int u = ks * 2 + ((lane >> 4) & 1);
                ldmx4(af[mi], as + r * 64 + ((u ^ ((r >> 1) & 3)) << 4));
            }
#pragma unroll
            for (int p = 0; p < 2; p++) {
                int r = wn + 16 * p + (lane & 7) + 8 * ((lane >> 4) & 1);
                int u = ks * 2 + ((lane >> 3) & 1);
                ldmx4(bf[p], bs + r * 64 + ((u ^ ((r >> 1) & 3)) << 4));
            }
#pragma unroll
            for (int mi = 0; mi < 4; mi++)
#pragma unroll
                for (int p = 0; p < 2; p++) {
                    mma16816(acc[mi][2 * p],     af[mi], bf[p][0], bf[p][1]);
                    mma16816(acc[mi][2 * p + 1], af[mi], bf[p][2], bf[p][3]);
                }
        }
    }

    // epilogue: approx distance = ||c||^2 - 2*dot  -> g_dist
    int gid = lane >> 2, tig = lane & 3;
#pragma unroll
    for (int mi = 0; mi < 4; mi++) {
        int row = m0 + wm + 16 * mi + gid;
#pragma unroll
        for (int nj = 0; nj < 4; nj++) {
            int c = wn + 8 * nj + 2 * tig;
            float cn0 = cns[c], cn1 = cns[c + 1];
            float2 v0 = make_float2(cn0 - 2.f * acc[mi][nj][0], cn1 - 2.f * acc[mi][nj][1]);
            float2 v1 = make_float2(cn0 - 2.f * acc[mi][nj][2], cn1 - 2.f * acc[mi][nj][3]);
            *reinterpret_cast<float2*>(g_dist + (size_t)row * E_ + n0 + c) = v0;
            *reinterpret_cast<float2*>(g_dist + (size_t)(row + 8) * E_ + n0 + c) = v1;
        }
    }
}

// ---------------- argmin + candidate collection (warp per row) ---------------
__global__ __launch_bounds__(256) void k_argmin() {
    int row = (blockIdx.x * 256 + threadIdx.x) >> 5;
    int lane = threadIdx.x & 31;
    if (row >= B_) return;
    const float4* dp = reinterpret_cast<const float4*>(g_dist + (size_t)row * E_);
    float4 v[4];
    float best = INFINITY;
    int bidx = 1 << 30;
#pragma unroll
    for (int j = 0; j < 4; j++) {
        v[j] = dp[lane + 32 * j];
        int c0 = (lane + 32 * j) * 4;
        const float* f = reinterpret_cast<const float*>(&v[j]);
#pragma unroll
        for (int e = 0; e < 4; e++) {
            float d = f[e];
            int c = c0 + e;
            if (d < best || (d == best && c < bidx)) { best = d; bidx = c; }
        }
    }
#pragma unroll
    for (int off = 16; off > 0; off >>= 1) {
        float ov = __shfl_xor_sync(0xffffffffu, best, off);
        int   oi = __shfl_xor_sync(0xffffffffu, bidx, off);
        if (ov < best || (ov == best && oi < bidx)) { best = ov; bidx = oi; }
    }
    float thr = best + MARGIN;
#pragma unroll
    for (int j = 0; j < 4; j++) {
        int c0 = (lane + 32 * j) * 4;
        const float* f = reinterpret_cast<const float*>(&v[j]);
#pragma unroll
        for (int e = 0; e < 4; e++) {
            if (f[e] <= thr) {
                int p = atomicAdd(&g_ncand[row], 1);
                if (p < 8) g_cand[row][p] = c0 + e;
            }
        }
    }
    if (lane == 0) g_idx[row] = bidx;
}

// ---------------- exact fp32 rescore of ambiguous rows -----------------------
__global__ __launch_bounds__(128) void k_rescore(const float* __restrict__ X,
                                                 const float* __restrict__ Cb) {
    int b = blockIdx.x;
    int n = g_ncand[b];
    if (n <= 1) return;                     // unambiguous: bf16 winner stands
    __shared__ float sh[128];
    const float4* x4 = reinterpret_cast<const float4*>(X + (size_t)b * D_);
    int total = (n <= 8) ? n : E_;          // >8 candidates: full exact scan
    float bestd = INFINITY;
    int besti = 1 << 30;
    for (int c = 0; c < total; c++) {
        int e = (n <= 8) ? g_cand[b][c] : c;
        const float4* c4 = reinterpret_cast<const float4*>(Cb + (size_t)e * D_);
        float s = 0.f;
        for (int i = threadIdx.x; i < D_ / 4; i += 128) {
            float4 xv = x4[i], cv = c4[i];
            s += xv.x * cv.x + xv.y * cv.y + xv.z * cv.z + xv.w * cv.w;
        }
        sh[threadIdx.x] = s;
        __syncthreads();
        for (int st = 64; st > 0; st >>= 1) {
            if (threadIdx.x < st) sh[threadIdx.x] += sh[threadIdx.x + st];
            __syncthreads();
        }
        float d = g_norm[e] - 2.f * sh[0];
        if (d < bestd || (d == bestd && e < besti)) { bestd = d; besti = e; }
        __syncthreads();
    }
    if (threadIdx.x == 0) g_idx[b] = besti;
}

// ---------------- outputs ---------------------------------------------------
__global__ __launch_bounds__(256) void k_out(const float* __restrict__ X,
                                             const float* __restrict__ Cb,
                                             float* __restrict__ outQ,
                                             float* __restrict__ outEnc) {
    int b = blockIdx.x;
    int t = threadIdx.x;
    int idx = g_idx[b];

    if (t == 0) atomicAdd(&g_hist[idx], 1);

    for (int e = t; e < E_; e += 256)
        outEnc[(size_t)b * E_ + e] = (e == idx) ? 1.f : 0.f;

    const float4* x4 = reinterpret_cast<const float4*>(X  + (size_t)b   * D_);
    const float4* q4 = reinterpret_cast<const float4*>(Cb + (size_t)idx * D_);
    float* o = outQ + (size_t)b * D_;

    float ls = 0.f;
    for (int i = t; i < D_ / 4; i += 256) {
        float4 x = x4[i];
        float4 q = q4[i];
        float dx = q.x - x.x, dy = q.y - x.y, dz = q.z - x.z, dw = q.w - x.w;
        o[4 * i + 0] = x.x + dx;
        o[4 * i + 1] = x.y + dy;
        o[4 * i + 2] = x.z + dz;
        o[4 * i + 3] = x.w + dw;
        ls += dx * dx + dy * dy + dz * dz + dw * dw;
    }

    __shared__ float sh[256];
    sh[t] = ls;
    __syncthreads();
    for (int st = 128; st > 0; st >>= 1) {
        if (t < st) sh[t] += sh[t + st];
        __syncthreads();
    }
    if (t == 0) atomicAdd(&g_loss, (double)sh[0]);
}

__global__ __launch_bounds__(512) void k_final(float* __restrict__ out) {
    __shared__ double sh[512];
    int t = threadIdx.x;
    double p = (double)g_hist[t] / (double)B_;
    sh[t] = p * log(p + 1e-10);
    __syncthreads();
    for (int st = 256; st > 0; st >>= 1) {
        if (t < st) sh[t] += sh[t + st];
        __syncthreads();
    }
    if (t == 0) {
        double mse = g_loss / ((double)B_ * (double)D_);
        out[0] = (float)(1.25 * mse);
        out[1 + (size_t)B_ * D_] = (float)exp(-sh[0]);
    }
}

// ---------------------------------------------------------------------------
extern "C" void kernel_launch(void* const* d_in, const int* in_sizes, int n_in,
                              void* d_out, int out_size) {
    (void)in_sizes; (void)n_in; (void)out_size;
    const float* X  = (const float*)d_in[0];
    const float* Cb = (const float*)d_in[1];
    float* out = (float*)d_out;

    float* outQ   = out + 1;
    float* outEnc = out + 2 + (size_t)B_ * D_;

    cudaFuncSetAttribute(k_gemm_mma, cudaFuncAttributeMaxDynamicSharedMemorySize,
                         SMEM_GEMM);

    k_init<<<32, 256>>>();
    k_convX<<<16384, 256>>>(X);
    k_normsC<<<E_, 256>>>(Cb);
    dim3 gg(E_ / 128, B_ / 128);
    k_gemm_mma<<<gg, 256, SMEM_GEMM>>>();
    k_argmin<<<B_ / 8, 256>>>();
    k_rescore<<<B_, 128>>>(X, Cb);
    k_out<<<B_, 256>>>(X, Cb, outQ, outEnc);
    k_final<<<1, 512>>>(out);
}